// round 2
// baseline (speedup 1.0000x reference)
#include <cuda_runtime.h>

// SSIM over 11x11 patches — coalesced-load version.
// img_pred: [4, 2048, 16, 121, 3] f32   (~190 MB)
// img_gt:   [2048, 16, 121, 3] f32      (~47.6 MB)
// out:      [4, 2048, 16] f32
//
// One warp per output (v,n,p). Warp streams the 363-float row linearly:
// lane l reads elements l, l+32, ..., fully coalesced (1 L1 wavefront per
// LDG instead of ~3-4 with the per-patch gather of R1). Channel of element
// e=(lane+32k) is (r+2k) mod 3 with r=lane%3, so lanes accumulate into
// congruence-class slots indexed by compile-time (2k)%3, then rotate by r
// once before the butterfly reduction. v fastest-varying in the warp index
// keeps the 4 views of one gt row in the same block -> gt from L1.

#define NV      4
#define NN      2048
#define NP      16
#define NPATCH  121
#define ROW     363   // 121 patches * 3 channels

__global__ __launch_bounds__(256) void ssim_kernel(
    const float* __restrict__ pred,
    const float* __restrict__ gt,
    float* __restrict__ out)
{
    __shared__ float we[ROW + 32];   // expanded per-element weights (+pad)

    const int tid = threadIdx.x;

    // Build expanded normalized gaussian window: we[e] = win[e/3].
    // 363 entries, 256 threads -> two passes.
    {
        const float inv2s2 = 1.0f / 4.5f;   // 1/(2*sigma^2), sigma=1.5
        float S = 0.0f;
        #pragma unroll
        for (int i = 0; i < 11; i++) {
            float d = (float)(i - 5);
            S += expf(-d * d * inv2s2);
        }
        const float invS2 = 1.0f / (S * S);
        for (int e = tid; e < ROW + 32; e += 256) {
            int patch = e / 3;
            if (patch >= NPATCH) patch = NPATCH - 1;   // padding, weight unused
            int py = patch / 11, px = patch % 11;
            float dy = (float)(py - 5), dx = (float)(px - 5);
            we[e] = expf(-(dx * dx + dy * dy) * inv2s2) * invS2;
        }
    }
    __syncthreads();

    const int warp = blockIdx.x * (blockDim.x >> 5) + (tid >> 5);
    const int lane = tid & 31;

    // warp -> (n, p, v) with v fastest (gt reuse within the block / L1)
    const int v = warp & 3;
    const int q = warp >> 2;       // n*16 + p
    const int n = q >> 4;
    const int p = q & 15;

    const float* __restrict__ pbase = pred + (size_t)((v * NN + n) * NP + p) * ROW;
    const float* __restrict__ gbase = gt   + (size_t)(n * NP + p) * ROW;

    // Congruence-class accumulators: slot j holds channel (lane%3 + j) % 3.
    float m1[3] = {0.f, 0.f, 0.f};
    float m2[3] = {0.f, 0.f, 0.f};
    float p2[3] = {0.f, 0.f, 0.f};
    float g2[3] = {0.f, 0.f, 0.f};
    float pg[3] = {0.f, 0.f, 0.f};

    // k = 0..10 full, k = 11 partial (363 = 11*32 + 11)
    #pragma unroll
    for (int k = 0; k < 12; k++) {
        const int e = k * 32 + lane;
        const int j = (2 * k) % 3;          // compile-time slot index
        float a = 0.f, b = 0.f, ww = 0.f;
        if (k < 11 || e < ROW) {
            a  = pbase[e];
            b  = gbase[e];
            ww = we[e];
        }
        m1[j] += ww * a;
        m2[j] += ww * b;
        p2[j] += ww * a * a;
        g2[j] += ww * b * b;
        pg[j] += ww * a * b;
    }

    // Rotate congruence slots into true channel order: ch[c] = slot[(c - r) mod 3]
    const int r = lane % 3;
    float cm1[3], cm2[3], cp2[3], cg2[3], cpg[3];
    #pragma unroll
    for (int c = 0; c < 3; c++) {
        // (c - r) mod 3 via two selects
        int j = (r == 0) ? c : (r == 1) ? (c + 2) % 3 : (c + 1) % 3;
        // j is a runtime 3-way select over compile-time layouts; expand manually:
        cm1[c] = (j == 0) ? m1[0] : (j == 1) ? m1[1] : m1[2];
        cm2[c] = (j == 0) ? m2[0] : (j == 1) ? m2[1] : m2[2];
        cp2[c] = (j == 0) ? p2[0] : (j == 1) ? p2[1] : p2[2];
        cg2[c] = (j == 0) ? g2[0] : (j == 1) ? g2[1] : g2[2];
        cpg[c] = (j == 0) ? pg[0] : (j == 1) ? pg[1] : pg[2];
    }

    // Warp butterfly reduction of the 15 channel accumulators.
    #pragma unroll
    for (int off = 16; off; off >>= 1) {
        #pragma unroll
        for (int c = 0; c < 3; c++) {
            cm1[c] += __shfl_xor_sync(0xFFFFFFFFu, cm1[c], off);
            cm2[c] += __shfl_xor_sync(0xFFFFFFFFu, cm2[c], off);
            cp2[c] += __shfl_xor_sync(0xFFFFFFFFu, cp2[c], off);
            cg2[c] += __shfl_xor_sync(0xFFFFFFFFu, cg2[c], off);
            cpg[c] += __shfl_xor_sync(0xFFFFFFFFu, cpg[c], off);
        }
    }

    if (lane == 0) {
        const float C1 = 1e-4f;   // 0.01^2
        const float C2 = 9e-4f;   // 0.03^2
        float acc = 0.0f;
        #pragma unroll
        for (int c = 0; c < 3; c++) {
            float mu1 = cm1[c], mu2 = cm2[c];
            float mu1sq = mu1 * mu1;
            float mu2sq = mu2 * mu2;
            float mu12  = mu1 * mu2;
            float s1 = cp2[c] - mu1sq;
            float s2 = cg2[c] - mu2sq;
            float s12 = cpg[c] - mu12;
            float num = (2.0f * mu12 + C1) * (2.0f * s12 + C2);
            float den = (mu1sq + mu2sq + C1) * (s1 + s2 + C2);
            acc += num / den;
        }
        out[(v * NN + n) * NP + p] = acc * (1.0f / 3.0f);
    }
}

extern "C" void kernel_launch(void* const* d_in, const int* in_sizes, int n_in,
                              void* d_out, int out_size)
{
    const float* pred = (const float*)d_in[0];   // img_pred [4,2048,16,121,3]
    const float* gt   = (const float*)d_in[1];   // img_gt   [2048,16,121,3]
    float* out = (float*)d_out;                  // [4,2048,16]

    const int total_warps = NV * NN * NP;        // 131072
    const int warps_per_block = 8;
    const int blocks = total_warps / warps_per_block;  // 16384

    ssim_kernel<<<blocks, 256>>>(pred, gt, out);
}

// round 3
// speedup vs baseline: 1.3636x; 1.3636x over previous
#include <cuda_runtime.h>

// SSIM over 11x11 patches — 4 outputs (views) per warp.
// img_pred: [4, 2048, 16, 121, 3] f32   (~190 MB)
// img_gt:   [2048, 16, 121, 3] f32      (~47.6 MB)
// out:      [4, 2048, 16] f32
//
// Warp -> (n,p). The warp streams the 363-float row coalesced (lane l reads
// element 32k+l, 1 cache line per LDG) for gt ONCE and for each of the 4
// views' pred. Channel of element e=(32k+lane) is ((2k)%3 + lane%3) mod 3,
// so accumulation goes into compile-time congruence slots; one register
// rotate by r=lane%3 at the end restores channel order (amortized over 4
// outputs). Reduction: values split into two self-contained 24-value halves
// (views 0,1 + gt) / (views 2,3 + gt): one fold across lane-bit-16, then a
// 4-level butterfly inside each 16-lane half. 120 shfl per 4 outputs vs 300.

#define NN      2048
#define NP      16
#define ROW     363                      // 121 patches * 3 channels
#define VSTRIDE ((size_t)NN * NP * ROW)  // floats per view

__global__ __launch_bounds__(256) void ssim_kernel(
    const float* __restrict__ pred,
    const float* __restrict__ gt,
    float* __restrict__ out)
{
    __shared__ float we[384];   // expanded per-element weights, zero-padded

    const int tid = threadIdx.x;

    // Build expanded normalized gaussian window: we[e] = win[e/3], 0 for e>=363.
    {
        const float inv2s2 = 1.0f / 4.5f;   // 1/(2*sigma^2), sigma=1.5
        float S = 0.0f;
        #pragma unroll
        for (int i = 0; i < 11; i++) {
            float d = (float)(i - 5);
            S += expf(-d * d * inv2s2);
        }
        const float invS2 = 1.0f / (S * S);
        for (int e = tid; e < 384; e += 256) {
            int patch = e / 3;
            int py = patch / 11, px = patch % 11;
            float dy = (float)(py - 5), dx = (float)(px - 5);
            float v = expf(-(dx * dx + dy * dy) * inv2s2) * invS2;
            we[e] = (e < ROW) ? v : 0.0f;
        }
    }
    __syncthreads();

    const int warp = blockIdx.x * (blockDim.x >> 5) + (tid >> 5);
    const int lane = tid & 31;

    const int n = warp >> 4;       // 0..2047
    const int p = warp & 15;       // 0..15

    const size_t rowoff = (size_t)(n * NP + p) * ROW;
    const float* __restrict__ g0 = gt + rowoff;
    const float* __restrict__ p0 = pred + rowoff;
    const float* __restrict__ p1 = p0 + VSTRIDE;
    const float* __restrict__ p2v = p0 + 2 * VSTRIDE;
    const float* __restrict__ p3 = p0 + 3 * VSTRIDE;

    // Congruence-slot accumulators. Slot j holds channel (j + lane%3) % 3.
    // Per view: m1 (sum w*a), q2 (sum w*a*a), pg (sum w*a*b).
    // gt stats duplicated per half so each 16-lane half is self-contained.
    float m1[4][3], q2[4][3], pg[4][3];
    float m2[2][3], g2[2][3];
    #pragma unroll
    for (int v = 0; v < 4; v++)
        #pragma unroll
        for (int j = 0; j < 3; j++) { m1[v][j] = 0.f; q2[v][j] = 0.f; pg[v][j] = 0.f; }
    #pragma unroll
    for (int h = 0; h < 2; h++)
        #pragma unroll
        for (int j = 0; j < 3; j++) { m2[h][j] = 0.f; g2[h][j] = 0.f; }

    // Main: k = 0..10 full warps of 32 elements (352 elems), tail below.
    #pragma unroll
    for (int k = 0; k < 11; k++) {
        const int e = k * 32 + lane;
        const int j = (2 * k) % 3;          // compile-time slot
        const float w = we[e];
        const float b = g0[e];
        const float wb = w * b;
        m2[0][j] += wb;       g2[0][j] += wb * b;
        m2[1][j] += wb;       g2[1][j] += wb * b;

        {   float a = p0[e]; float wa = w * a;
            m1[0][j] += wa; q2[0][j] += wa * a; pg[0][j] += wa * b; }
        {   float a = p1[e]; float wa = w * a;
            m1[1][j] += wa; q2[1][j] += wa * a; pg[1][j] += wa * b; }
        {   float a = p2v[e]; float wa = w * a;
            m1[2][j] += wa; q2[2][j] += wa * a; pg[2][j] += wa * b; }
        {   float a = p3[e]; float wa = w * a;
            m1[3][j] += wa; q2[3][j] += wa * a; pg[3][j] += wa * b; }
    }
    // Tail: k=11, elements 352..362 (11 valid lanes), slot j = 22%3 = 1.
    if (lane < 11) {
        const int e = 352 + lane;
        const int j = 1;
        const float w = we[e];
        const float b = g0[e];
        const float wb = w * b;
        m2[0][j] += wb;       g2[0][j] += wb * b;
        m2[1][j] += wb;       g2[1][j] += wb * b;
        {   float a = p0[e]; float wa = w * a;
            m1[0][j] += wa; q2[0][j] += wa * a; pg[0][j] += wa * b; }
        {   float a = p1[e]; float wa = w * a;
            m1[1][j] += wa; q2[1][j] += wa * a; pg[1][j] += wa * b; }
        {   float a = p2v[e]; float wa = w * a;
            m1[2][j] += wa; q2[2][j] += wa * a; pg[2][j] += wa * b; }
        {   float a = p3[e]; float wa = w * a;
            m1[3][j] += wa; q2[3][j] += wa * a; pg[3][j] += wa * b; }
    }

    // Rotate congruence slots into true channel order.
    // True channel c lives in slot (c - r + 3) % 3, r = lane % 3:
    //   r=0: (s0,s1,s2)  r=1: (s2,s0,s1)  r=2: (s1,s2,s0)
    const int r = lane - (lane / 3) * 3;
    const bool r1f = (r == 1);
    const bool r2f = (r == 2);
    #define ROT3(s) do { \
        float t0 = (s)[0], t1 = (s)[1], t2 = (s)[2]; \
        (s)[0] = r1f ? t2 : (r2f ? t1 : t0); \
        (s)[1] = r1f ? t0 : (r2f ? t2 : t1); \
        (s)[2] = r1f ? t1 : (r2f ? t0 : t2); \
    } while (0)
    #pragma unroll
    for (int v = 0; v < 4; v++) { ROT3(m1[v]); ROT3(q2[v]); ROT3(pg[v]); }
    #pragma unroll
    for (int h = 0; h < 2; h++) { ROT3(m2[h]); ROT3(g2[h]); }
    #undef ROT3

    // Pack the half this lane will carry after the fold:
    //  half A (lanes 0-15):  views 0,1 + gt copy 0
    //  half B (lanes 16-31): views 2,3 + gt copy 1
    // layout: [0..2] m1_lo  [3..5] q2_lo  [6..8] pg_lo
    //         [9..11] m1_hi [12..14] q2_hi [15..17] pg_hi
    //         [18..20] m2   [21..23] g2
    const bool hi = (lane & 16) != 0;
    float val[24];
    #pragma unroll
    for (int j = 0; j < 3; j++) {
        float kA, kB;
        // fold helper: keep own half's value, add partner's (other-half) value
        #define FOLD(slotA, slotB, idx) \
            kA = (slotA); kB = (slotB); \
            { float keep = hi ? kB : kA; float send = hi ? kA : kB; \
              val[idx] = keep + __shfl_xor_sync(0xFFFFFFFFu, send, 16); }
        FOLD(m1[0][j], m1[2][j], 0 + j);
        FOLD(q2[0][j], q2[2][j], 3 + j);
        FOLD(pg[0][j], pg[2][j], 6 + j);
        FOLD(m1[1][j], m1[3][j], 9 + j);
        FOLD(q2[1][j], q2[3][j], 12 + j);
        FOLD(pg[1][j], pg[3][j], 15 + j);
        FOLD(m2[0][j], m2[1][j], 18 + j);
        FOLD(g2[0][j], g2[1][j], 21 + j);
        #undef FOLD
    }

    // Butterfly within each 16-lane half.
    #pragma unroll
    for (int off = 8; off; off >>= 1) {
        #pragma unroll
        for (int i = 0; i < 24; i++)
            val[i] += __shfl_xor_sync(0xFFFFFFFFu, val[i], off);
    }

    // Epilogue: each lane computes SSIM for its half's two views.
    const float C1 = 1e-4f;   // 0.01^2
    const float C2 = 9e-4f;   // 0.03^2
    float ssim_lo = 0.f, ssim_hi_v = 0.f;
    #pragma unroll
    for (int c = 0; c < 3; c++) {
        float mu2  = val[18 + c];
        float mu2sq = mu2 * mu2;
        float s2   = val[21 + c] - mu2sq;
        {   // view lo
            float mu1 = val[0 + c];
            float mu1sq = mu1 * mu1;
            float mu12  = mu1 * mu2;
            float s1  = val[3 + c] - mu1sq;
            float s12 = val[6 + c] - mu12;
            float num = (2.0f * mu12 + C1) * (2.0f * s12 + C2);
            float den = (mu1sq + mu2sq + C1) * (s1 + s2 + C2);
            ssim_lo += __fdividef(num, den);
        }
        {   // view hi
            float mu1 = val[9 + c];
            float mu1sq = mu1 * mu1;
            float mu12  = mu1 * mu2;
            float s1  = val[12 + c] - mu1sq;
            float s12 = val[15 + c] - mu12;
            float num = (2.0f * mu12 + C1) * (2.0f * s12 + C2);
            float den = (mu1sq + mu2sq + C1) * (s1 + s2 + C2);
            ssim_hi_v += __fdividef(num, den);
        }
    }

    // Writers: lanes 0,1 (views 0,1) and 16,17 (views 2,3).
    if ((lane & 14) == 0) {
        int sel  = lane & 1;
        int view = ((lane >> 4) << 1) | sel;
        float res = (sel ? ssim_hi_v : ssim_lo) * (1.0f / 3.0f);
        out[(view * NN + n) * NP + p] = res;
    }
}

extern "C" void kernel_launch(void* const* d_in, const int* in_sizes, int n_in,
                              void* d_out, int out_size)
{
    const float* pred = (const float*)d_in[0];   // img_pred [4,2048,16,121,3]
    const float* gt   = (const float*)d_in[1];   // img_gt   [2048,16,121,3]
    float* out = (float*)d_out;                  // [4,2048,16]

    const int total_warps = NN * NP;             // 32768 warps, 4 outputs each
    const int warps_per_block = 8;
    const int blocks = total_warps / warps_per_block;  // 4096

    ssim_kernel<<<blocks, 256>>>(pred, gt, out);
}